// round 3
// baseline (speedup 1.0000x reference)
#include <cuda_runtime.h>
#include <math.h>

// Problem constants
#define NN 1024          // nodes
#define BB 64            // batch
#define NB (NN*BB)       // 65536 rows in (N,B,*) layout
#define HH 128           // hidden
#define F0 130           // layer0 concat features (I + H)
#define F0P 136          // padded to multiple of 8
#define F1P 256          // layer1 concat features (H + H)
#define BF0 (BB*F0P)     // 8704  (= 68*128)
#define BF1 (BB*F1P)     // 16384 (= 128*128)

// ---------------- static device scratch (no allocation allowed) ----------------
__device__ float g_G[(size_t)4096*1024];        // [A0; 2A0^2; A1; 2A1^2]
__device__ float g_x[(size_t)NB*256];           // concat input, stride F0P or F1P
__device__ float g_y[(size_t)4*1024*BF1];       // G @ x  (4 slices of (N,B,F))
__device__ float g_gate[(size_t)NB*256];        // sigmoid gates: r=[0:128), u=[128:256)
__device__ float g_s0[(size_t)NB*HH];
__device__ float g_s1[(size_t)NB*HH];
__device__ float g_Wg0[5*F0P*256];
__device__ float g_Wc0[5*F0P*128];
__device__ float g_Wg1[5*F1P*256];
__device__ float g_Wc1[5*F1P*128];

// ---------------- SGEMM: C(M,Ncols) = alpha * A(M,K) @ B(K,Ncols) ----------------
// 128x128 block, BK=8, 256 threads, 8x8 per-thread tile, double-buffered smem.
__global__ __launch_bounds__(256)
void sgemm_graph_kernel(int M, int Ncols, int Kdim,
                        const float* __restrict__ A, int lda,
                        const float* __restrict__ B, int ldb,
                        float* __restrict__ C, int ldc, float alpha)
{
    __shared__ float As[2][8][128];
    __shared__ float Bs[2][8][128];
    const int tid = threadIdx.x;
    const int m0 = blockIdx.y * 128;
    const int n0 = blockIdx.x * 128;
    const int arow = tid >> 1;
    const int acol = (tid & 1) << 2;
    const int brow = tid >> 5;
    const int bcol = (tid & 31) << 2;
    const float* Ap = A + (size_t)(m0 + arow) * lda + acol;
    const float* Bp = B + (size_t)brow * ldb + n0 + bcol;
    const int tx = tid & 15, ty = tid >> 4;

    float acc[8][8];
#pragma unroll
    for (int i = 0; i < 8; i++)
#pragma unroll
        for (int j = 0; j < 8; j++) acc[i][j] = 0.f;

    float4 a4 = *(const float4*)Ap;
    float4 b4 = *(const float4*)Bp;
    As[0][acol+0][arow] = a4.x; As[0][acol+1][arow] = a4.y;
    As[0][acol+2][arow] = a4.z; As[0][acol+3][arow] = a4.w;
    *(float4*)(&Bs[0][brow][bcol]) = b4;
    __syncthreads();

    const int ntiles = Kdim >> 3;
    for (int it = 0; it < ntiles; ++it) {
        const int buf = it & 1;
        if (it + 1 < ntiles) {
            const int k0 = (it + 1) << 3;
            a4 = *(const float4*)(Ap + k0);
            b4 = *(const float4*)(Bp + (size_t)k0 * ldb);
        }
#pragma unroll
        for (int kk = 0; kk < 8; ++kk) {
            float ar[8], br[8];
            *(float4*)&ar[0] = *(const float4*)&As[buf][kk][ty*8];
            *(float4*)&ar[4] = *(const float4*)&As[buf][kk][ty*8+4];
            *(float4*)&br[0] = *(const float4*)&Bs[buf][kk][tx*8];
            *(float4*)&br[4] = *(const float4*)&Bs[buf][kk][tx*8+4];
#pragma unroll
            for (int i = 0; i < 8; i++)
#pragma unroll
                for (int j = 0; j < 8; j++)
                    acc[i][j] = fmaf(ar[i], br[j], acc[i][j]);
        }
        if (it + 1 < ntiles) {
            const int nb = buf ^ 1;
            As[nb][acol+0][arow] = a4.x; As[nb][acol+1][arow] = a4.y;
            As[nb][acol+2][arow] = a4.z; As[nb][acol+3][arow] = a4.w;
            *(float4*)(&Bs[nb][brow][bcol]) = b4;
            __syncthreads();
        }
    }
#pragma unroll
    for (int i = 0; i < 8; i++) {
        float* Cp = C + (size_t)(m0 + ty*8 + i) * ldc + n0 + tx*8;
        float4 v0 = make_float4(alpha*acc[i][0], alpha*acc[i][1], alpha*acc[i][2], alpha*acc[i][3]);
        float4 v1 = make_float4(alpha*acc[i][4], alpha*acc[i][5], alpha*acc[i][6], alpha*acc[i][7]);
        *(float4*)Cp = v0; *(float4*)(Cp + 4) = v1;
    }
}

// ---------------- Multi-term weight GEMM with fused epilogue ----------------
// C(NB, O) = bias + X(NB,Fp)@W[0] + sum_{t=1..4} Yslice_t(NB,Fp)@W[t]
// mode 0: gate  -> g-style: gateOut[row*256+col] = sigmoid(v)       (O=256)
// mode 1: cand  -> state[row*128+col] = u*s + (1-u)*tanh(v)          (O=128)
__global__ __launch_bounds__(256)
void sgemm_weight_kernel(int O, int Fp,
                         const float* __restrict__ X,
                         const float* __restrict__ Yb,
                         const float* __restrict__ W,
                         const float* __restrict__ bias,
                         float* __restrict__ gateOut,
                         const float* __restrict__ gateIn,
                         float* __restrict__ state,
                         int mode)
{
    __shared__ float As[2][8][128];
    __shared__ float Bs[2][8][128];
    const int tid = threadIdx.x;
    const int m0 = blockIdx.y * 128;
    const int n0 = blockIdx.x * 128;
    const int arow = tid >> 1;
    const int acol = (tid & 1) << 2;
    const int brow = tid >> 5;
    const int bcol = (tid & 31) << 2;
    const int tx = tid & 15, ty = tid >> 4;
    const int tilesPerTerm = Fp >> 3;
    const int ntiles = 5 * tilesPerTerm;
    const size_t termStride = (size_t)NB * Fp;

    float acc[8][8];
#pragma unroll
    for (int i = 0; i < 8; i++)
#pragma unroll
        for (int j = 0; j < 8; j++) acc[i][j] = 0.f;

    // prologue: tile 0 (term 0, k0 = 0)
    float4 a4 = *(const float4*)(X + (size_t)(m0 + arow) * Fp + acol);
    float4 b4 = *(const float4*)(W + (size_t)brow * O + n0 + bcol);
    As[0][acol+0][arow] = a4.x; As[0][acol+1][arow] = a4.y;
    As[0][acol+2][arow] = a4.z; As[0][acol+3][arow] = a4.w;
    *(float4*)(&Bs[0][brow][bcol]) = b4;
    __syncthreads();

    for (int tt = 0; tt < ntiles; ++tt) {
        const int buf = tt & 1;
        if (tt + 1 < ntiles) {
            const int t2 = tt + 1;
            const int term = t2 / tilesPerTerm;
            const int k0 = (t2 - term * tilesPerTerm) << 3;
            const float* Ap = (term == 0) ? X : (Yb + (size_t)(term - 1) * termStride);
            a4 = *(const float4*)(Ap + (size_t)(m0 + arow) * Fp + k0 + acol);
            b4 = *(const float4*)(W + ((size_t)term * Fp + k0 + brow) * O + n0 + bcol);
        }
#pragma unroll
        for (int kk = 0; kk < 8; ++kk) {
            float ar[8], br[8];
            *(float4*)&ar[0] = *(const float4*)&As[buf][kk][ty*8];
            *(float4*)&ar[4] = *(const float4*)&As[buf][kk][ty*8+4];
            *(float4*)&br[0] = *(const float4*)&Bs[buf][kk][tx*8];
            *(float4*)&br[4] = *(const float4*)&Bs[buf][kk][tx*8+4];
#pragma unroll
            for (int i = 0; i < 8; i++)
#pragma unroll
                for (int j = 0; j < 8; j++)
                    acc[i][j] = fmaf(ar[i], br[j], acc[i][j]);
        }
        if (tt + 1 < ntiles) {
            const int nb = buf ^ 1;
            As[nb][acol+0][arow] = a4.x; As[nb][acol+1][arow] = a4.y;
            As[nb][acol+2][arow] = a4.z; As[nb][acol+3][arow] = a4.w;
            *(float4*)(&Bs[nb][brow][bcol]) = b4;
            __syncthreads();
        }
    }

#pragma unroll
    for (int i = 0; i < 8; i++) {
        const int row = m0 + ty*8 + i;
#pragma unroll
        for (int j = 0; j < 8; j++) {
            const int col = n0 + tx*8 + j;
            float v = acc[i][j] + bias[col];
            if (mode == 0) {
                gateOut[(size_t)row * 256 + col] = 1.f / (1.f + expf(-v));
            } else {
                float u = gateIn[(size_t)row * 256 + 128 + col];
                float s = state[(size_t)row * 128 + col];
                state[(size_t)row * 128 + col] = u * s + (1.f - u) * tanhf(v);
            }
        }
    }
}

// ---------------- elementwise helpers ----------------
__global__ void copy_G_kernel(const float* __restrict__ sup)
{
    size_t i = (size_t)blockIdx.x * blockDim.x + threadIdx.x;
    const size_t half = (size_t)NN * NN;
    const size_t total = 2 * half;
    for (; i < total; i += (size_t)gridDim.x * blockDim.x) {
        float v = sup[i];
        size_t dst = (i < half) ? i : i + half;   // A0 -> rows 0..1023, A1 -> rows 2048..3071
        g_G[dst] = v;
    }
}

// dst (5*Fp, O): block0 = W00+W10-W02-W12 ; then W01, W02, W11, W12. Pad rows zero.
__global__ void build_wcat_kernel(float* __restrict__ dst, const float* __restrict__ src,
                                  int F, int Fp, int O, int count)
{
    int idx = blockIdx.x * blockDim.x + threadIdx.x;
    if (idx >= count) return;
    const int blk = idx / (Fp * O);
    const int rem = idx - blk * Fp * O;
    const int f = rem / O;
    const int o = rem - f * O;
    float v = 0.f;
    if (f < F) {
        #define WSK(s,k) src[((((size_t)(s))*3 + (k)) * F + f) * O + o]
        switch (blk) {
            case 0: v = WSK(0,0) + WSK(1,0) - WSK(0,2) - WSK(1,2); break;
            case 1: v = WSK(0,1); break;
            case 2: v = WSK(0,2); break;
            case 3: v = WSK(1,1); break;
            case 4: v = WSK(1,2); break;
        }
        #undef WSK
    }
    dst[idx] = v;
}

// layer0 concat: x[nb, 0:2]=inp, [2:130]= (r*)s0, [130:136]=0   (stride F0P)
__global__ void build_x0_kernel(const float* __restrict__ inp_t,
                                const float* __restrict__ s0,
                                const float* __restrict__ gate, int useReset)
{
    const int nb = blockIdx.x;
    const int c = threadIdx.x;
    if (c >= F0P) return;
    const int n = nb >> 6, b = nb & 63;
    float v;
    if (c < 2) {
        v = inp_t[((size_t)b * NN + n) * 2 + c];
    } else if (c < F0) {
        const int j = c - 2;
        float s = s0[(size_t)nb * HH + j];
        if (useReset) s *= gate[(size_t)nb * 256 + j];
        v = s;
    } else {
        v = 0.f;
    }
    g_x[(size_t)nb * F0P + c] = v;
}

// layer1 concat: x[nb,0:128]=s0_new, [128:256]=(r*)s1   (stride 256)
__global__ void build_x1_kernel(const float* __restrict__ s0,
                                const float* __restrict__ s1,
                                const float* __restrict__ gate, int useReset)
{
    const int nb = blockIdx.x;
    const int c = threadIdx.x;  // 0..127
    g_x[(size_t)nb * F1P + c] = s0[(size_t)nb * HH + c];
    float s = s1[(size_t)nb * HH + c];
    if (useReset) s *= gate[(size_t)nb * 256 + c];
    g_x[(size_t)nb * F1P + 128 + c] = s;
}

// out (2, B, N, H) from states (N, B, H)
__global__ void write_out_kernel(float* __restrict__ out)
{
    const int nb = blockIdx.x;
    const int h = threadIdx.x;  // 0..127
    const int n = nb >> 6, b = nb & 63;
    out[(((size_t)0 * BB + b) * NN + n) * HH + h] = g_s0[(size_t)nb * HH + h];
    out[(((size_t)1 * BB + b) * NN + n) * HH + h] = g_s1[(size_t)nb * HH + h];
}

// ---------------- host orchestration ----------------
extern "C" void kernel_launch(void* const* d_in, const int* in_sizes, int n_in,
                              void* d_out, int out_size)
{
    const float* inputs   = (const float*)d_in[0];
    const float* supports = (const float*)d_in[1];
    const float* ruW0 = (const float*)d_in[2];
    const float* rub0 = (const float*)d_in[3];
    const float* hW0  = (const float*)d_in[4];
    const float* hb0  = (const float*)d_in[5];
    const float* ruW1 = (const float*)d_in[6];
    const float* rub1 = (const float*)d_in[7];
    const float* hW1  = (const float*)d_in[8];
    const float* hb1  = (const float*)d_in[9];
    float* out = (float*)d_out;

    float *G, *X, *Y, *GATE, *S0, *S1, *Wg0, *Wc0, *Wg1, *Wc1;
    cudaGetSymbolAddress((void**)&G,    g_G);
    cudaGetSymbolAddress((void**)&X,    g_x);
    cudaGetSymbolAddress((void**)&Y,    g_y);
    cudaGetSymbolAddress((void**)&GATE, g_gate);
    cudaGetSymbolAddress((void**)&S0,   g_s0);
    cudaGetSymbolAddress((void**)&S1,   g_s1);
    cudaGetSymbolAddress((void**)&Wg0,  g_Wg0);
    cudaGetSymbolAddress((void**)&Wc0,  g_Wc0);
    cudaGetSymbolAddress((void**)&Wg1,  g_Wg1);
    cudaGetSymbolAddress((void**)&Wc1,  g_Wc1);

    // ---- prologue: G = [A0; 2A0^2; A1; 2A1^2], W concatenations, zero states ----
    copy_G_kernel<<<4096, 512>>>(supports);
    sgemm_graph_kernel<<<dim3(8, 8), 256>>>(NN, NN, NN,
        supports, NN, supports, NN, G + (size_t)NN * NN, NN, 2.f);
    sgemm_graph_kernel<<<dim3(8, 8), 256>>>(NN, NN, NN,
        supports + (size_t)NN * NN, NN, supports + (size_t)NN * NN, NN,
        G + (size_t)3 * NN * NN, NN, 2.f);

    int c0 = 5 * F0P * 256; build_wcat_kernel<<<(c0 + 255) / 256, 256>>>(Wg0, ruW0, F0, F0P, 256, c0);
    int c1 = 5 * F0P * 128; build_wcat_kernel<<<(c1 + 255) / 256, 256>>>(Wc0, hW0,  F0, F0P, 128, c1);
    int c2 = 5 * F1P * 256; build_wcat_kernel<<<(c2 + 255) / 256, 256>>>(Wg1, ruW1, F1P, F1P, 256, c2);
    int c3 = 5 * F1P * 128; build_wcat_kernel<<<(c3 + 255) / 256, 256>>>(Wc1, hW1,  F1P, F1P, 128, c3);

    cudaMemsetAsync(S0, 0, (size_t)NB * HH * sizeof(float));
    cudaMemsetAsync(S1, 0, (size_t)NB * HH * sizeof(float));

    // ---- recurrence ----
    for (int t = 0; t < 12; ++t) {
        const float* inp_t = inputs + (size_t)t * BB * NN * 2;

        // ---- layer 0 ----
        build_x0_kernel<<<NB, 160>>>(inp_t, S0, GATE, 0);
        sgemm_graph_kernel<<<dim3(BF0 / 128, 32), 256>>>(4096, BF0, NN, G, NN, X, BF0, Y, BF0, 1.f);
        sgemm_weight_kernel<<<dim3(2, 512), 256>>>(256, F0P, X, Y, Wg0, rub0, GATE, (const float*)0, (float*)0, 0);

        build_x0_kernel<<<NB, 160>>>(inp_t, S0, GATE, 1);
        sgemm_graph_kernel<<<dim3(BF0 / 128, 32), 256>>>(4096, BF0, NN, G, NN, X, BF0, Y, BF0, 1.f);
        sgemm_weight_kernel<<<dim3(1, 512), 256>>>(128, F0P, X, Y, Wc0, hb0, (float*)0, GATE, S0, 1);

        // ---- layer 1 ----
        build_x1_kernel<<<NB, 128>>>(S0, S1, GATE, 0);
        sgemm_graph_kernel<<<dim3(BF1 / 128, 32), 256>>>(4096, BF1, NN, G, NN, X, BF1, Y, BF1, 1.f);
        sgemm_weight_kernel<<<dim3(2, 512), 256>>>(256, F1P, X, Y, Wg1, rub1, GATE, (const float*)0, (float*)0, 0);

        build_x1_kernel<<<NB, 128>>>(S0, S1, GATE, 1);
        sgemm_graph_kernel<<<dim3(BF1 / 128, 32), 256>>>(4096, BF1, NN, G, NN, X, BF1, Y, BF1, 1.f);
        sgemm_weight_kernel<<<dim3(1, 512), 256>>>(128, F1P, X, Y, Wc1, hb1, (float*)0, GATE, S1, 1);
    }

    write_out_kernel<<<NB, 128>>>(out);
}

// round 6
// speedup vs baseline: 1.9935x; 1.9935x over previous
#include <cuda_runtime.h>
#include <cuda_fp16.h>
#include <math.h>
#include <stdint.h>

#define NN 1024
#define BB 64
#define NB 65536
#define HH 128
#define F0R 130
#define FP0 192
#define FP1 256
#define BF0 (BB*FP0)
#define BF1 (BB*FP1)
#define K50 (5*FP0)
#define K51 (5*FP1)
#define PITCH 40   // halves per smem row (80B: 16B-aligned, bank-conflict-free)

// ---------------- static device scratch ----------------
__device__ __align__(128) __half g_Ah[(size_t)NB*K51];
__device__ __align__(128) __half g_Al[(size_t)NB*K51];
__device__ __align__(128) __half g_Xth[(size_t)BF1*NN];
__device__ __align__(128) __half g_Xtl[(size_t)BF1*NN];
__device__ __align__(128) __half g_Gh[(size_t)4096*NN];
__device__ __align__(128) __half g_Gl[(size_t)4096*NN];
__device__ __align__(128) float  g_sq[(size_t)2*NN*NN];
__device__ __align__(128) __half g_Wg0h[256*K50], g_Wg0l[256*K50];
__device__ __align__(128) __half g_Wc0h[128*K50], g_Wc0l[128*K50];
__device__ __align__(128) __half g_Wg1h[256*K51], g_Wg1l[256*K51];
__device__ __align__(128) __half g_Wc1h[128*K51], g_Wc1l[128*K51];
__device__ __align__(128) float  g_gate[(size_t)NB*256];
__device__ __align__(128) float  g_s0[(size_t)NB*HH];
__device__ __align__(128) float  g_s1[(size_t)NB*HH];

// ---------------- helpers ----------------
__device__ __forceinline__ uint32_t smem_u32(const void* p){
    uint32_t a; asm("{ .reg .u64 t; cvta.to.shared.u64 t, %1; cvt.u32.u64 %0, t; }":"=r"(a):"l"(p)); return a;
}
__device__ __forceinline__ void cp16(uint32_t d, const void* s){
    asm volatile("cp.async.cg.shared.global [%0], [%1], 16;\n"::"r"(d),"l"(s):"memory");
}
__device__ __forceinline__ void ldmA(uint32_t* a, uint32_t addr){
    asm volatile("ldmatrix.sync.aligned.m8n8.x4.shared.b16 {%0,%1,%2,%3}, [%4];"
        : "=r"(a[0]),"=r"(a[1]),"=r"(a[2]),"=r"(a[3]) : "r"(addr));
}
__device__ __forceinline__ void ldmB(uint32_t* b, uint32_t addr){
    asm volatile("ldmatrix.sync.aligned.m8n8.x2.shared.b16 {%0,%1}, [%2];"
        : "=r"(b[0]),"=r"(b[1]) : "r"(addr));
}
__device__ __forceinline__ void mma16816(float* d, const uint32_t* a, const uint32_t* b){
    asm volatile("mma.sync.aligned.m16n8k16.row.col.f32.f16.f16.f32 "
        "{%0,%1,%2,%3},{%4,%5,%6,%7},{%8,%9},{%0,%1,%2,%3};"
        : "+f"(d[0]),"+f"(d[1]),"+f"(d[2]),"+f"(d[3])
        : "r"(a[0]),"r"(a[1]),"r"(a[2]),"r"(a[3]),"r"(b[0]),"r"(b[1]));
}

// ---------------- fp16-split HGEMM (tile 128x128, BK=32, mma.sync) ----------------
// D = sum over 3 segs of Aseg(128 x segK) @ Bseg(128 x segK)^T, both K-major.
// mode 0: split-write Y into g_Ah/g_Al terms 1..4 (graph GEMM)
// mode 1: gate[row*256+c] = sigmoid(v + bias[c])
// mode 2: state[row*128+c] = u*s + (1-u)*tanh(v + bias[c])
struct GArgs {
    const __half *A0,*A1,*A2,*B0,*B1,*B2;
    int lda, ldb, segChunks, mode, fp, k5;
    const float* bias; float* gate; float* state;
};

__global__ __launch_bounds__(256,2) void hgemm(GArgs g)
{
    __shared__ __align__(16) __half sA[2][128*PITCH];
    __shared__ __align__(16) __half sB[2][128*PITCH];
    const int tid = threadIdx.x;
    const int wid = tid >> 5, lane = tid & 31;
    const int m0 = blockIdx.y * 128, n0 = blockIdx.x * 128;
    const int mbase = (wid >> 2) * 64, nbase = (wid & 3) * 32;

    const __half* Aseg[3] = {g.A0, g.A1, g.A2};
    const __half* Bseg[3] = {g.B0, g.B1, g.B2};
    const int nch = 3 * g.segChunks;

    float acc[4][4][4];
#pragma unroll
    for (int i = 0; i < 4; i++)
#pragma unroll
        for (int j = 0; j < 4; j++)
#pragma unroll
            for (int k = 0; k < 4; k++) acc[i][j][k] = 0.f;

    const int lr = tid >> 2;            // 0..63: row pair base
    const int lc = (tid & 3) * 8;       // chunk of 8 halves
    const uint32_t sA0 = smem_u32(&sA[0][0]), sB0 = smem_u32(&sB[0][0]);

    auto fill = [&](int c, int buf){
        const int seg = c / g.segChunks;
        const int k0 = (c - seg * g.segChunks) * 32;
        const __half* Ab = Aseg[seg] + (size_t)m0 * g.lda + k0;
        const __half* Bb = Bseg[seg] + (size_t)n0 * g.ldb + k0;
        const uint32_t ab = sA0 + buf * 128*PITCH*2;
        const uint32_t bb = sB0 + buf * 128*PITCH*2;
#pragma unroll
        for (int h = 0; h < 2; h++) {
            const int r = lr + h * 64;
            cp16(ab + (r*PITCH + lc)*2, Ab + (size_t)r * g.lda + lc);
            cp16(bb + (r*PITCH + lc)*2, Bb + (size_t)r * g.ldb + lc);
        }
        asm volatile("cp.async.commit_group;\n":::"memory");
    };

    fill(0, 0);
    for (int c = 0; c < nch; c++) {
        const int buf = c & 1;
        if (c + 1 < nch) {
            fill(c + 1, buf ^ 1);
            asm volatile("cp.async.wait_group 1;\n":::"memory");
        } else {
            asm volatile("cp.async.wait_group 0;\n":::"memory");
        }
        __syncthreads();
        const uint32_t ab = sA0 + buf * 128*PITCH*2;
        const uint32_t bb = sB0 + buf * 128*PITCH*2;
#pragma unroll
        for (int ks = 0; ks < 2; ks++) {
            uint32_t afr[4][4], bfr[4][2];
#pragma unroll
            for (int mi = 0; mi < 4; mi++) {
                const int r = mbase + mi*16 + (lane & 15);
                const int ch = ks*16 + (lane >> 4) * 8;
                ldmA(afr[mi], ab + (r*PITCH + ch)*2);
            }
#pragma unroll
            for (int ni = 0; ni < 4; ni++) {
                const int l = lane & 15;
                const int r = nbase + ni*8 + (l & 7);
                const int ch = ks*16 + (l >> 3) * 8;
                ldmB(bfr[ni], bb + (r*PITCH + ch)*2);
            }
#pragma unroll
            for (int mi = 0; mi < 4; mi++)
#pragma unroll
                for (int ni = 0; ni < 4; ni++)
                    mma16816(acc[mi][ni], afr[mi], bfr[ni]);
        }
        __syncthreads();
    }

    // ---------------- epilogue ----------------
#pragma unroll
    for (int mi = 0; mi < 4; mi++) {
#pragma unroll
        for (int half2i = 0; half2i < 2; half2i++) {     // c0,c1 then c2,c3 (row+8)
            const int rg = m0 + mbase + mi*16 + (lane >> 2) + half2i*8;
#pragma unroll
            for (int ni = 0; ni < 4; ni++) {
                const int cg = n0 + nbase + ni*8 + (lane & 3)*2;
                const float v0 = acc[mi][ni][half2i*2 + 0];
                const float v1 = acc[mi][ni][half2i*2 + 1];
                if (g.mode == 0) {
                    const int s = rg >> 10, n = rg & 1023;
                    const int b = cg / g.fp, f = cg - b * g.fp;
                    const size_t base = (size_t)(n*64 + b) * g.k5 + (size_t)(s+1) * g.fp + f;
                    const __half h0 = __float2half_rn(v0), h1 = __float2half_rn(v1);
                    __half2 hh; hh.x = h0; hh.y = h1;
                    __half2 ll;
                    ll.x = __float2half_rn(v0 - __half2float(h0));
                    ll.y = __float2half_rn(v1 - __half2float(h1));
                    *(__half2*)(g_Ah + base) = hh;
                    *(__half2*)(g_Al + base) = ll;
                } else if (g.mode == 1) {
                    float2 o;
                    o.x = 1.f/(1.f + expf(-(v0 + g.bias[cg+0])));
                    o.y = 1.f/(1.f + expf(-(v1 + g.bias[cg+1])));
                    *(float2*)(g.gate + (size_t)rg*256 + cg) = o;
                } else {
                    const float2 u = *(const float2*)(g.gate + (size_t)rg*256 + 128 + cg);
                    const float2 so = *(const float2*)(g.state + (size_t)rg*128 + cg);
                    float2 o;
                    o.x = u.x*so.x + (1.f-u.x)*tanhf(v0 + g.bias[cg+0]);
                    o.y = u.y*so.y + (1.f-u.y)*tanhf(v1 + g.bias[cg+1]);
                    *(float2*)(g.state + (size_t)rg*128 + cg) = o;
                }
            }
        }
    }
}

// ---------------- fp32 SGEMM for prologue: C = 2 * A @ A (1024^3) ----------------
__global__ __launch_bounds__(256)
void sgemm_sq(const float* __restrict__ A, float* __restrict__ C)
{
    __shared__ float As[2][8][128];
    __shared__ float Bs[2][8][128];
    const int tid = threadIdx.x;
    const int m0 = blockIdx.y * 128, n0 = blockIdx.x * 128;
    const int arow = tid >> 1, acol = (tid & 1) << 2;
    const int brow = tid >> 5, bcol = (tid & 31) << 2;
    const float* Ap = A + (size_t)(m0 + arow) * NN + acol;
    const float* Bp = A + (size_t)brow * NN + n0 + bcol;
    const int tx = tid & 15, ty = tid >> 4;
    float acc[8][8];
#pragma unroll
    for (int i = 0; i < 8; i++)
#pragma unroll
        for (int j = 0; j < 8; j++) acc[i][j] = 0.f;
    float4 a4 = *(const float4*)Ap, b4 = *(const float4*)Bp;
    As[0][acol+0][arow]=a4.x; As[0][acol+1][arow]=a4.y; As[0][acol+2][arow]=a4.z; As[0][acol+3][arow]=a4.w;
    *(float4*)(&Bs[0][brow][bcol]) = b4;
    __syncthreads();
    for (int it = 0; it < 128; ++it) {
        const int buf = it & 1;
        if (it + 1 < 128) {
            const int k0 = (it + 1) << 3;
            a4 = *(const float4*)(Ap + k0);
            b4 = *(const float4*)(Bp + (size_t)k0 * NN);
        }
#pragma unroll
        for (int kk = 0; kk < 8; ++kk) {
            float ar[8], br[8];
            *(float4*)&ar[0] = *(const float4*)&As[buf][kk][ty*8];
            *(float4*)&ar[4] = *(const float4*)&As[buf][kk][ty*8+4];
            *(float4*)&br[0] = *(const float4*)&Bs[buf][kk][tx*8];
            *(float4*)&br[4] = *(const float4*)&Bs[buf][kk][tx*8+4];
#pragma unroll
            for (int i = 0; i < 8; i++)
#pragma unroll
                for (int j = 0; j < 8; j++) acc[i][j] = fmaf(ar[i], br[j], acc[i][j]);
        }
        if (it + 1 < 128) {
            const int nb2 = buf ^ 1;
            As[nb2][acol+0][arow]=a4.x; As[nb2][acol+1][arow]=a4.y; As[nb2][acol+2][arow]=a4.z; As[nb2][acol+3][arow]=a4.w;
            *(float4*)(&Bs[nb2][brow][bcol]) = b4;
            __syncthreads();
        }
    }
#pragma unroll
    for (int i = 0; i < 8; i++) {
        float* Cp = C + (size_t)(m0 + ty*8 + i) * NN + n0 + tx*8;
#pragma unroll
        for (int j = 0; j < 8; j++) Cp[j] = 2.f * acc[i][j];
    }
}

// ---------------- builders ----------------
__device__ __forceinline__ float xval0(const float* __restrict__ inp, int n, int b, int f, int reset){
    if (f < 2) return inp[((size_t)b*NN + n)*2 + f];
    if (f < F0R) {
        const int j = f - 2;
        float s = g_s0[((size_t)n*64 + b)*HH + j];
        if (reset) s *= g_gate[((size_t)n*64 + b)*256 + j];
        return s;
    }
    return 0.f;
}
__device__ __forceinline__ float xval1(int n, int b, int f, int reset){
    if (f < HH) return g_s0[((size_t)n*64 + b)*HH + f];
    const int j = f - HH;
    float s = g_s1[((size_t)n*64 + b)*HH + j];
    if (reset) s *= g_gate[((size_t)n*64 + b)*256 + j];
    return s;
}

__global__ void build_a(const float* __restrict__ inp, int layer, int reset, int fp, int k5){
    const int row = blockIdx.x, f = threadIdx.x;
    const int n = row >> 6, b = row & 63;
    const float v = layer ? xval1(n, b, f, reset) : xval0(inp, n, b, f, reset);
    __half h = __float2half_rn(v);
    g_Ah[(size_t)row*k5 + f] = h;
    g_Al[(size_t)row*k5 + f] = __float2half_rn(v - __half2float(h));
}

__global__ void build_xt(const float* __restrict__ inp, int layer, int reset, int fp){
    __shared__ float t[32][33];
    const int b = blockIdx.z, f0 = blockIdx.y*32, nt = blockIdx.x*32;
    const int tx = threadIdx.x, ty = threadIdx.y;
#pragma unroll
    for (int k = 0; k < 4; k++) {
        const int n = nt + ty + 8*k, f = f0 + tx;
        t[ty + 8*k][tx] = layer ? xval1(n, b, f, reset) : xval0(inp, n, b, f, reset);
    }
    __syncthreads();
#pragma unroll
    for (int k = 0; k < 4; k++) {
        const int f = f0 + ty + 8*k, n = nt + tx;
        const float v = t[tx][ty + 8*k];
        __half h = __float2half_rn(v);
        const size_t o = ((size_t)b*fp + f)*NN + n;
        g_Xth[o] = h;
        g_Xtl[o] = __float2half_rn(v - __half2float(h));
    }
}

__global__ void split_G(const float* __restrict__ sup){
    size_t i = (size_t)blockIdx.x * blockDim.x + threadIdx.x;
    if (i >= (size_t)4096*NN) return;
    const int row = (int)(i >> 10), col = (int)(i & 1023);
    const int slice = row >> 10, n = row & 1023;
    float v;
    if (slice == 0)      v = sup[(size_t)n*NN + col];
    else if (slice == 1) v = g_sq[(size_t)n*NN + col];
    else if (slice == 2) v = sup[(size_t)NN*NN + (size_t)n*NN + col];
    else                 v = g_sq[(size_t)NN*NN + (size_t)n*NN + col];
    __half h = __float2half_rn(v);
    g_Gh[i] = h;
    g_Gl[i] = __float2half_rn(v - __half2float(h));
}

__global__ void build_wt(__half* __restrict__ Wh, __half* __restrict__ Wl,
                         const float* __restrict__ src, int O, int F, int fp){
    const int k5 = 5*fp;
    int i = blockIdx.x * blockDim.x + threadIdx.x;
    if (i >= O*k5) return;
    const int o = i / k5, k = i - o*k5;
    const int t = k / fp, f = k - t*fp;
    float v = 0.f;
    if (f < F) {
        #define WSK(s,kx) src[((((size_t)(s))*3 + (kx))*F + f)*O + o]
        switch (t) {
            case 0: v = WSK(0,0)+WSK(1,0)-WSK(0,2)-WSK(1,2); break;
            case 1: v = WSK(0,1); break;
            case 2: v = WSK(0,2); break;
            case 3: v = WSK(1,1); break;
            case 4: v = WSK(1,2); break;
        }
        #undef WSK
    }
    __half h = __float2half_rn(v);
    Wh[i] = h;
    Wl[i] = __float2half_rn(v - __half2float(h));
}

__global__ void write_out(float* __restrict__ out){
    const int nb = blockIdx.x, h = threadIdx.x;
    const int n = nb >> 6, b = nb & 63;
    out[(((size_t)0*BB + b)*NN + n)*HH + h] = g_s0[(size_t)nb*HH + h];
    out[(((size_t)1*BB + b)*NN + n)*HH + h] = g_s1[(size_t)nb*HH + h];
}

// ---------------- host ----------------
static void run_gemm(dim3 grid, const __half* A0, const __half* A1, const __half* A2,
                     const __half* B0, const __half* B1, const __half* B2,
                     int lda, int ldb, int segChunks, int mode, int fp, int k5,
                     const float* bias, float* gate, float* state)
{
    GArgs g{A0,A1,A2,B0,B1,B2,lda,ldb,segChunks,mode,fp,k5,bias,gate,state};
    hgemm<<<grid, 256>>>(g);
}

extern "C" void kernel_launch(void* const* d_in, const int* in_sizes, int n_in,
                              void* d_out, int out_size)
{
    const float* inputs = (const float*)d_in[0];
    const float* sup    = (const float*)d_in[1];
    const float* ruW0 = (const float*)d_in[2];
    const float* rub0 = (const float*)d_in[3];
    const float* hW0  = (const float*)d_in[4];
    const float* hb0  = (const float*)d_in[5];
    const float* ruW1 = (const float*)d_in[6];
    const float* rub1 = (const float*)d_in[7];
    const float* hW1  = (const float*)d_in[8];
    const float* hb1  = (const float*)d_in[9];
    float* out = (float*)d_out;

    float *SQ, *S0, *S1, *GATE;
    __half *Ah, *Al, *Xth, *Xtl, *Gh, *Gl;
    __half *Wg0h,*Wg0l,*Wc0h,*Wc0l,*Wg1h,*Wg1l,*Wc1h,*Wc1l;
    cudaGetSymbolAddress((void**)&SQ, g_sq);
    cudaGetSymbolAddress((void**)&S0, g_s0);
    cudaGetSymbolAddress((void**)&S1, g_s1);
    cudaGetSymbolAddress((void**)&GATE, g_gate);
    cudaGetSymbolAddress((void**)&Ah, g_Ah);
    cudaGetSymbolAddress((void**)&Al, g_Al);
    cudaGetSymbolAddress((void**)&Xth, g_Xth);
    cudaGetSymbolAddress((void**)&Xtl, g_Xtl);
    cudaGetSymbolAddress((void**)&Gh, g_Gh);
    cudaGetSymbolAddress((void**)&Gl, g_Gl);
    cudaGetSymbolAddress((void**)&Wg0h, g_Wg0h); cudaGetSymbolAddress((void**)&Wg0l, g_Wg0l);
    cudaGetSymbolAddress((void**)&Wc0h, g_Wc0h); cudaGetSymbolAddress((void**)&Wc0l, g_Wc0l);
    cudaGetSymbolAddress((void**)&Wg1h, g_Wg1h); cudaGetSymbolAddress((void**)&Wg1l, g_Wg1l);
    cudaGetSymbolAddress((void**)&Wc1h, g_Wc1h); cudaGetSymbolAddress((void**)&Wc1l, g_Wc1l);

    // prologue
    sgemm_sq<<<dim3(8,8), 256>>>(sup, SQ);
    sgemm_sq<<<dim3(8,8), 256>>>(sup + (size_t)NN*NN, SQ + (size_t)NN*NN);
    split_G<<<(4096*1024)/256, 256>>>(sup);
    build_wt<<<(256*K50+255)/256, 256>>>(Wg0h, Wg0l, ruW0, 256, F0R, FP0);
    build_wt<<<(128*K50+255)/256, 256>>>(Wc0h, Wc0l, hW0, 128, F0R, FP0);
    build_wt<<<(256*K51+255)/256, 256>>>(Wg1h, Wg1l, ruW1, 256, FP1, FP1);
    build_wt<<<(128*K51+255)/256, 256>>>(Wc1h, Wc1l, hW1, 128, FP1, FP1);
    cudaMemsetAsync(S0, 0, (size_t)NB*HH*4);
    cudaMemsetAsync(S1, 0, (size_t)NB*HH*4);

    const dim3 gg0(BF0/128, 32), gg1(BF1/128, 32);
    const dim3 wgate(2, 512), wcand(1, 512);
    const dim3 xt0(NN/32, FP0/32, BB), xt1(NN/32, FP1/32, BB);
    const dim3 bxt(32, 8);

    for (int t = 0; t < 12; ++t) {
        const float* inp = inputs + (size_t)t * BB * NN * 2;
        // layer 0 gate
        build_a<<<NB, FP0>>>(inp, 0, 0, FP0, K50);
        build_xt<<<xt0, bxt>>>(inp, 0, 0, FP0);
        run_gemm(gg0, Gh, Gh, Gl, Xth, Xtl, Xth, NN, NN, 32, 0, FP0, K50, 0, 0, 0);
        run_gemm(wgate, Ah, Ah, Al, Wg0h, Wg0l, Wg0h, K50, K50, 30, 1, FP0, K50, rub0, GATE, 0);
        // layer 0 candidate
        build_a<<<NB, FP0>>>(inp, 0, 1, FP0, K50);
        build_xt<<<xt0, bxt>>>(inp, 0, 1, FP0);
        run_gemm(gg0, Gh, Gh, Gl, Xth, Xtl, Xth, NN, NN, 32, 0, FP0, K50, 0, 0, 0);
        run_gemm(wcand, Ah, Ah, Al, Wc0h, Wc0l, Wc0h, K50, K50, 30, 2, FP0, K50, hb0, GATE, S0);
        // layer 1 gate
        build_a<<<NB, FP1>>>(inp, 1, 0, FP1, K51);
        build_xt<<<xt1, bxt>>>(inp, 1, 0, FP1);
        run_gemm(gg1, Gh, Gh, Gl, Xth, Xtl, Xth, NN, NN, 32, 0, FP1, K51, 0, 0, 0);
        run_gemm(wgate, Ah, Ah, Al, Wg1h, Wg1l, Wg1h, K51, K51, 40, 1, FP1, K51, rub1, GATE, 0);
        // layer 1 candidate
        build_a<<<NB, FP1>>>(inp, 1, 1, FP1, K51);
        build_xt<<<xt1, bxt>>>(inp, 1, 1, FP1);
        run_gemm(gg1, Gh, Gh, Gl, Xth, Xtl, Xth, NN, NN, 32, 0, FP1, K51, 0, 0, 0);
        run_gemm(wcand, Ah, Ah, Al, Wc1h, Wc1l, Wc1h, K51, K51, 40, 2, FP1, K51, hb1, GATE, S1);
    }
    write_out<<<NB, 128>>>(out);
}

// round 7
// speedup vs baseline: 2.4151x; 1.2115x over previous
#include <cuda_runtime.h>
#include <cuda_fp16.h>
#include <math.h>
#include <stdint.h>

#define NN 1024
#define BB 64
#define NB 65536
#define HH 128
#define F0R 130
#define FP0 192
#define FP1 256
#define BF0 (BB*FP0)
#define BF1 (BB*FP1)
#define K50 (5*FP0)
#define K51 (5*FP1)
#define PITCH 40                 // halves per smem row (80B, 16B-aligned, conflict-free)
#define TSH (128*PITCH)          // halves per tile
#define SMEM_SZ (2*4*TSH*2)      // 2 buffers x 4 tiles x TSH halves x 2B = 81920

// ---------------- static device scratch ----------------
__device__ __align__(128) __half g_Ah[(size_t)NB*K51];
__device__ __align__(128) __half g_Al[(size_t)NB*K51];
__device__ __align__(128) __half g_Xth[(size_t)BF1*NN];
__device__ __align__(128) __half g_Xtl[(size_t)BF1*NN];
__device__ __align__(128) __half g_Gh[(size_t)4096*NN];
__device__ __align__(128) __half g_Gl[(size_t)4096*NN];
__device__ __align__(128) float  g_sq[(size_t)2*NN*NN];
__device__ __align__(128) __half g_Wg0h[256*K50], g_Wg0l[256*K50];
__device__ __align__(128) __half g_Wc0h[128*K50], g_Wc0l[128*K50];
__device__ __align__(128) __half g_Wg1h[256*K51], g_Wg1l[256*K51];
__device__ __align__(128) __half g_Wc1h[128*K51], g_Wc1l[128*K51];
__device__ __align__(128) float  g_gate[(size_t)NB*256];
__device__ __align__(128) float  g_s0[(size_t)NB*HH];
__device__ __align__(128) float  g_s1[(size_t)NB*HH];

// ---------------- helpers ----------------
__device__ __forceinline__ uint32_t smem_u32(const void* p){
    uint32_t a; asm("{ .reg .u64 t; cvta.to.shared.u64 t, %1; cvt.u32.u64 %0, t; }":"=r"(a):"l"(p)); return a;
}
__device__ __forceinline__ void cp16(uint32_t d, const void* s){
    asm volatile("cp.async.cg.shared.global [%0], [%1], 16;\n"::"r"(d),"l"(s):"memory");
}
__device__ __forceinline__ void ldmA(uint32_t* a, uint32_t addr){
    asm volatile("ldmatrix.sync.aligned.m8n8.x4.shared.b16 {%0,%1,%2,%3}, [%4];"
        : "=r"(a[0]),"=r"(a[1]),"=r"(a[2]),"=r"(a[3]) : "r"(addr));
}
__device__ __forceinline__ void ldmB(uint32_t* b, uint32_t addr){
    asm volatile("ldmatrix.sync.aligned.m8n8.x2.shared.b16 {%0,%1}, [%2];"
        : "=r"(b[0]),"=r"(b[1]) : "r"(addr));
}
__device__ __forceinline__ void mma16816(float* d, const uint32_t* a, const uint32_t* b){
    asm volatile("mma.sync.aligned.m16n8k16.row.col.f32.f16.f16.f32 "
        "{%0,%1,%2,%3},{%4,%5,%6,%7},{%8,%9},{%0,%1,%2,%3};"
        : "+f"(d[0]),"+f"(d[1]),"+f"(d[2]),"+f"(d[3])
        : "r"(a[0]),"r"(a[1]),"r"(a[2]),"r"(a[3]),"r"(b[0]),"r"(b[1]));
}

// ---------------- fp16-split HGEMM v2: quad-tile, 3 products per chunk ----------------
// acc = Ah@Bh^T + Ah@Bl^T + Al@Bh^T over K in chunks of 32; A,B K-major.
// mode 0: split-write Y into g_Ah/g_Al terms 1..4 (graph GEMM)
// mode 1: gate[row*256+c] = sigmoid(v + bias[c])
// mode 2: state[row*128+c] = u*s + (1-u)*tanh(v + bias[c])
struct GArgs {
    const __half *Ah,*Al,*Bh,*Bl;
    int lda, ldb, nch, mode, fp, k5;
    const float* bias; float* gate; float* state;
};

__global__ __launch_bounds__(256,2) void hgemm(GArgs g)
{
    extern __shared__ __align__(16) __half sm[];
    const int tid = threadIdx.x;
    const int wid = tid >> 5, lane = tid & 31;
    const int m0 = blockIdx.y * 128, n0 = blockIdx.x * 128;
    const int mbase = (wid >> 2) * 64, nbase = (wid & 3) * 32;
    const uint32_t smb = smem_u32(sm);

    float acc[4][4][4];
#pragma unroll
    for (int i = 0; i < 4; i++)
#pragma unroll
        for (int j = 0; j < 4; j++)
#pragma unroll
            for (int k = 0; k < 4; k++) acc[i][j][k] = 0.f;

    const int lr = tid >> 2;            // 0..63
    const int lc = (tid & 3) * 8;       // 0,8,16,24

    auto fill = [&](int c, int buf){
        const int k0 = c * 32;
        const __half* srcs[4] = {
            g.Ah + (size_t)m0 * g.lda + k0,
            g.Al + (size_t)m0 * g.lda + k0,
            g.Bh + (size_t)n0 * g.ldb + k0,
            g.Bl + (size_t)n0 * g.ldb + k0 };
        const int lds[4] = { g.lda, g.lda, g.ldb, g.ldb };
        const uint32_t base = smb + buf * 4*TSH*2;
#pragma unroll
        for (int t = 0; t < 4; t++) {
            const uint32_t tb = base + t * TSH*2;
#pragma unroll
            for (int h = 0; h < 2; h++) {
                const int r = lr + h * 64;
                cp16(tb + (r*PITCH + lc)*2, srcs[t] + (size_t)r * lds[t] + lc);
            }
        }
        asm volatile("cp.async.commit_group;\n":::"memory");
    };

    fill(0, 0);
    for (int c = 0; c < g.nch; c++) {
        const int buf = c & 1;
        if (c + 1 < g.nch) {
            fill(c + 1, buf ^ 1);
            asm volatile("cp.async.wait_group 1;\n":::"memory");
        } else {
            asm volatile("cp.async.wait_group 0;\n":::"memory");
        }
        __syncthreads();
        const uint32_t base = smb + buf * 4*TSH*2;
        const uint32_t aH = base, aL = base + TSH*2;
        const uint32_t bH = base + 2*TSH*2, bL = base + 3*TSH*2;
#pragma unroll
        for (int ks = 0; ks < 2; ks++) {
            const int chA = ks*16 + (lane >> 4) * 8;
            const int lB = lane & 15;
            const int chB = ks*16 + (lB >> 3) * 8;
            uint32_t afr[4][4], bfr[4][2];
            // --- product 1: Ah @ Bl ---
#pragma unroll
            for (int mi = 0; mi < 4; mi++) {
                const int r = mbase + mi*16 + (lane & 15);
                ldmA(afr[mi], aH + (r*PITCH + chA)*2);
            }
#pragma unroll
            for (int ni = 0; ni < 4; ni++) {
                const int r = nbase + ni*8 + (lB & 7);
                ldmB(bfr[ni], bL + (r*PITCH + chB)*2);
            }
#pragma unroll
            for (int mi = 0; mi < 4; mi++)
#pragma unroll
                for (int ni = 0; ni < 4; ni++)
                    mma16816(acc[mi][ni], afr[mi], bfr[ni]);
            // --- product 2: Ah @ Bh (reuse afr) ---
#pragma unroll
            for (int ni = 0; ni < 4; ni++) {
                const int r = nbase + ni*8 + (lB & 7);
                ldmB(bfr[ni], bH + (r*PITCH + chB)*2);
            }
#pragma unroll
            for (int mi = 0; mi < 4; mi++)
#pragma unroll
                for (int ni = 0; ni < 4; ni++)
                    mma16816(acc[mi][ni], afr[mi], bfr[ni]);
            // --- product 3: Al @ Bh (reuse bfr) ---
#pragma unroll
            for (int mi = 0; mi < 4; mi++) {
                const int r = mbase + mi*16 + (lane & 15);
                ldmA(afr[mi], aL + (r*PITCH + chA)*2);
            }
#pragma unroll
            for (int mi = 0; mi < 4; mi++)
#pragma unroll
                for (int ni = 0; ni < 4; ni++)
                    mma16816(acc[mi][ni], afr[mi], bfr[ni]);
        }
        __syncthreads();
    }

    // ---------------- epilogue ----------------
#pragma unroll
    for (int mi = 0; mi < 4; mi++) {
#pragma unroll
        for (int h2 = 0; h2 < 2; h2++) {
            const int rg = m0 + mbase + mi*16 + (lane >> 2) + h2*8;
#pragma unroll
            for (int ni = 0; ni < 4; ni++) {
                const int cg = n0 + nbase + ni*8 + (lane & 3)*2;
                const float v0 = acc[mi][ni][h2*2 + 0];
                const float v1 = acc[mi][ni][h2*2 + 1];
                if (g.mode == 0) {
                    const int s = rg >> 10, n = rg & 1023;
                    const int b = cg / g.fp, f = cg - b * g.fp;
                    const size_t base = (size_t)(n*64 + b) * g.k5 + (size_t)(s+1) * g.fp + f;
                    const __half h0 = __float2half_rn(v0), h1 = __float2half_rn(v1);
                    __half2 hh; hh.x = h0; hh.y = h1;
                    __half2 ll;
                    ll.x = __float2half_rn(v0 - __half2float(h0));
                    ll.y = __float2half_rn(v1 - __half2float(h1));
                    *(__half2*)(g_Ah + base) = hh;
                    *(__half2*)(g_Al + base) = ll;
                } else if (g.mode == 1) {
                    float2 o;
                    o.x = 1.f/(1.f + expf(-(v0 + g.bias[cg+0])));
                    o.y = 1.f/(1.f + expf(-(v1 + g.bias[cg+1])));
                    *(float2*)(g.gate + (size_t)rg*256 + cg) = o;
                } else {
                    const float2 u = *(const float2*)(g.gate + (size_t)rg*256 + 128 + cg);
                    const float2 so = *(const float2*)(g.state + (size_t)rg*128 + cg);
                    float2 o;
                    o.x = u.x*so.x + (1.f-u.x)*tanhf(v0 + g.bias[cg+0]);
                    o.y = u.y*so.y + (1.f-u.y)*tanhf(v1 + g.bias[cg+1]);
                    *(float2*)(g.state + (size_t)rg*128 + cg) = o;
                }
            }
        }
    }
}

// ---------------- fp32 SGEMM for prologue: C = 2 * A @ A (1024^3) ----------------
__global__ __launch_bounds__(256)
void sgemm_sq(const float* __restrict__ A, float* __restrict__ C)
{
    __shared__ float As[2][8][128];
    __shared__ float Bs[2][8][128];
    const int tid = threadIdx.x;
    const int m0 = blockIdx.y * 128, n0 = blockIdx.x * 128;
    const int arow = tid >> 1, acol = (tid & 1) << 2;
    const int brow = tid >> 5, bcol = (tid & 31) << 2;
    const float* Ap = A + (size_t)(m0 + arow) * NN + acol;
    const float* Bp = A + (size_t)brow * NN + n0 + bcol;
    const int tx = tid & 15, ty = tid >> 4;
    float acc[8][8];
#pragma unroll
    for (int i = 0; i < 8; i++)
#pragma unroll
        for (int j = 0; j < 8; j++) acc[i][j] = 0.f;
    float4 a4 = *(const float4*)Ap, b4 = *(const float4*)Bp;
    As[0][acol+0][arow]=a4.x; As[0][acol+1][arow]=a4.y; As[0][acol+2][arow]=a4.z; As[0][acol+3][arow]=a4.w;
    *(float4*)(&Bs[0][brow][bcol]) = b4;
    __syncthreads();
    for (int it = 0; it < 128; ++it) {
        const int buf = it & 1;
        if (it + 1 < 128) {
            const int k0 = (it + 1) << 3;
            a4 = *(const float4*)(Ap + k0);
            b4 = *(const float4*)(Bp + (size_t)k0 * NN);
        }
#pragma unroll
        for (int kk = 0; kk < 8; ++kk) {
            float ar[8], br[8];
            *(float4*)&ar[0] = *(const float4*)&As[buf][kk][ty*8];
            *(float4*)&ar[4] = *(const float4*)&As[buf][kk][ty*8+4];
            *(float4*)&br[0] = *(const float4*)&Bs[buf][kk][tx*8];
            *(float4*)&br[4] = *(const float4*)&Bs[buf][kk][tx*8+4];
#pragma unroll
            for (int i = 0; i < 8; i++)
#pragma unroll
                for (int j = 0; j < 8; j++) acc[i][j] = fmaf(ar[i], br[j], acc[i][j]);
        }
        if (it + 1 < 128) {
            const int nb2 = buf ^ 1;
            As[nb2][acol+0][arow]=a4.x; As[nb2][acol+1][arow]=a4.y; As[nb2][acol+2][arow]=a4.z; As[nb2][acol+3][arow]=a4.w;
            *(float4*)(&Bs[nb2][brow][bcol]) = b4;
            __syncthreads();
        }
    }
#pragma unroll
    for (int i = 0; i < 8; i++) {
        float* Cp = C + (size_t)(m0 + ty*8 + i) * NN + n0 + tx*8;
#pragma unroll
        for (int j = 0; j < 8; j++) Cp[j] = 2.f * acc[i][j];
    }
}

// ---------------- builders ----------------
__device__ __forceinline__ float xval0(const float* __restrict__ inp, int n, int b, int f, int reset){
    if (f < 2) return inp[((size_t)b*NN + n)*2 + f];
    if (f < F0R) {
        const int j = f - 2;
        float s = g_s0[((size_t)n*64 + b)*HH + j];
        if (reset) s *= g_gate[((size_t)n*64 + b)*256 + j];
        return s;
    }
    return 0.f;
}
__device__ __forceinline__ float xval1(int n, int b, int f, int reset){
    if (f < HH) return g_s0[((size_t)n*64 + b)*HH + f];
    const int j = f - HH;
    float s = g_s1[((size_t)n*64 + b)*HH + j];
    if (reset) s *= g_gate[((size_t)n*64 + b)*256 + j];
    return s;
}

__global__ void build_a(const float* __restrict__ inp, int layer, int reset, int fp, int k5){
    const int row = blockIdx.x, f = threadIdx.x;
    const int n = row >> 6, b = row & 63;
    const float v = layer ? xval1(n, b, f, reset) : xval0(inp, n, b, f, reset);
    __half h = __float2half_rn(v);
    g_Ah[(size_t)row*k5 + f] = h;
    g_Al[(size_t)row*k5 + f] = __float2half_rn(v - __half2float(h));
}

__global__ void build_xt(const float* __restrict__ inp, int layer, int reset, int fp){
    __shared__ float t[32][33];
    const int b = blockIdx.z, f0 = blockIdx.y*32, nt = blockIdx.x*32;
    const int tx = threadIdx.x, ty = threadIdx.y;
#pragma unroll
    for (int k = 0; k < 4; k++) {
        const int n = nt + ty + 8*k, f = f0 + tx;
        t[ty + 8*k][tx] = layer ? xval1(n, b, f, reset) : xval0(inp, n, b, f, reset);
    }
    __syncthreads();
#pragma unroll
    for (int k = 0; k < 4; k++) {
        const int f = f0 + ty + 8*k, n = nt + tx;
        const float v = t[tx][ty + 8*k];
        __half h = __float2half_rn(v);
        const size_t o = ((size_t)b*fp + f)*NN + n;
        g_Xth[o] = h;
        g_Xtl[o] = __float2half_rn(v - __half2float(h));
    }
}

__global__ void split_G(const float* __restrict__ sup){
    size_t i = (size_t)blockIdx.x * blockDim.x + threadIdx.x;
    if (i >= (size_t)4096*NN) return;
    const int row = (int)(i >> 10), col = (int)(i & 1023);
    const int slice = row >> 10, n = row & 1023;
    float v;
    if (slice == 0)      v = sup[(size_t)n*NN + col];
    else if (slice == 1) v = g_sq[(size_t)n*NN + col];
    else if (slice == 2) v = sup[(size_t)NN*NN + (size_t)n*NN + col];
    else                 v = g_sq[(size_t)NN*NN + (size_t)n*NN + col];
    __half h = __float2half_rn(v);
    g_Gh[i] = h;
    g_Gl[i] = __float2half_rn(v - __half2float(h));
}

__global__ void build_wt(__half* __restrict__ Wh, __half* __restrict__ Wl,
                         const float* __restrict__ src, int O, int F, int fp){
    const int k5 = 5*fp;
    int i = blockIdx.x * blockDim.x + threadIdx.x;
    if (i >= O*k5) return;
    const int o = i / k5, k = i - o*k5;
    const int t = k / fp, f = k - t*fp;
    float v = 0.f;
    if (f < F) {
        #define WSK(s,kx) src[((((size_t)(s))*3 + (kx))*F + f)*O + o]
        switch (t) {
            case 0: v = WSK(0,0)+WSK(1,0)-WSK(0,2)-WSK(1,2); break;
            case 1: v = WSK(0,1); break;
            case 2: v = WSK(0,2); break;
            case 3: v = WSK(1,1); break;
            case 4: v = WSK(1,2); break;
        }
        #undef WSK
    }
    __half h = __float2half_rn(v);
    Wh[i] = h;
    Wl[i] = __float2half_rn(v - __half2float(h));
}

__global__ void write_out(float* __restrict__ out){
    const int nb = blockIdx.x, h = threadIdx.x;
    const int n = nb >> 6, b = nb & 63;
    out[(((size_t)0*BB + b)*NN + n)*HH + h] = g_s0[(size_t)nb*HH + h];
    out[(((size_t)1*BB + b)*NN + n)*HH + h] = g_s1[(size_t)nb*HH + h];
}

// ---------------- host ----------------
static void run_gemm(dim3 grid, const __half* Ah, const __half* Al,
                     const __half* Bh, const __half* Bl,
                     int lda, int ldb, int nch, int mode, int fp, int k5,
                     const float* bias, float* gate, float* state)
{
    GArgs g{Ah,Al,Bh,Bl,lda,ldb,nch,mode,fp,k5,bias,gate,state};
    hgemm<<<grid, 256, SMEM_SZ>>>(g);
}

extern "C" void kernel_launch(void* const* d_in, const int* in_sizes, int n_in,
                              void* d_out, int out_size)
{
    const float* inputs = (const float*)d_in[0];
    const float* sup    = (const float*)d_in[1];
    const float* ruW0 = (const float*)d_in[2];
    const float* rub0 = (const float*)d_in[3];
    const float* hW0  = (const float*)d_in[4];
    const float* hb0  = (const float*)d_in[5];
    const float* ruW1 = (const float*)d_in[6];
    const float* rub1 = (const float*)d_in[7];
    const float* hW1  = (const float*)d_in[8];
    const float* hb1  = (const float*)d_in[9];
    float* out = (float*)d_out;

    cudaFuncSetAttribute(hgemm, cudaFuncAttributeMaxDynamicSharedMemorySize, SMEM_SZ);

    float *SQ, *S0, *S1, *GATE;
    __half *Ah, *Al, *Xth, *Xtl, *Gh, *Gl;
    __half *Wg0h,*Wg0l,*Wc0h,*Wc0l,*Wg1h,*Wg1l,*Wc1h,*Wc1l;
    cudaGetSymbolAddress((void**)&SQ, g_sq);
    cudaGetSymbolAddress((void**)&S0, g_s0);
    cudaGetSymbolAddress((void**)&S1, g_s1);
    cudaGetSymbolAddress((void**)&GATE, g_gate);
    cudaGetSymbolAddress((void**)&Ah, g_Ah);
    cudaGetSymbolAddress((void**)&Al, g_Al);
    cudaGetSymbolAddress((void**)&Xth, g_Xth);
    cudaGetSymbolAddress((void**)&Xtl, g_Xtl);
    cudaGetSymbolAddress((void**)&Gh, g_Gh);
    cudaGetSymbolAddress((void**)&Gl, g_Gl);
    cudaGetSymbolAddress((void**)&Wg0h, g_Wg0h); cudaGetSymbolAddress((void**)&Wg0l, g_Wg0l);
    cudaGetSymbolAddress((void**)&Wc0h, g_Wc0h); cudaGetSymbolAddress((void**)&Wc0l, g_Wc0l);
    cudaGetSymbolAddress((void**)&Wg1h, g_Wg1h); cudaGetSymbolAddress((void**)&Wg1l, g_Wg1l);
    cudaGetSymbolAddress((void**)&Wc1h, g_Wc1h); cudaGetSymbolAddress((void**)&Wc1l, g_Wc1l);

    // prologue
    sgemm_sq<<<dim3(8,8), 256>>>(sup, SQ);
    sgemm_sq<<<dim3(8,8), 256>>>(sup + (size_t)NN*NN, SQ + (size_t)NN*NN);
    split_G<<<(4096*1024)/256, 256>>>(sup);
    build_wt<<<(256*K50+255)/256, 256>>>(Wg0h, Wg0l, ruW0, 256, F0R, FP0);
    build_wt<<<(128*K50+255)/256, 256>>>(Wc0h, Wc0l, hW0, 128, F0R, FP0);
    build_wt<<<(256*K51+255)/256, 256>>>(Wg1h, Wg1l, ruW1, 256, FP1, FP1);
    build_wt<<<(128*K51+255)/256, 256>>>(Wc1h, Wc1l, hW1, 128, FP1, FP1);
    cudaMemsetAsync(S0, 0, (size_t)NB*HH*4);
    cudaMemsetAsync(S1, 0, (size_t)NB*HH*4);

    const dim3 gg0(BF0/128, 32), gg1(BF1/128, 32);
    const dim3 wgate(2, 512), wcand(1, 512);
    const dim3 xt0(NN/32, FP0/32, BB), xt1(NN/32, FP1/32, BB);
    const dim3 bxt(32, 8);

    for (int t = 0; t < 12; ++t) {
        const float* inp = inputs + (size_t)t * BB * NN * 2;
        // layer 0 gate
        build_a<<<NB, FP0>>>(inp, 0, 0, FP0, K50);
        build_xt<<<xt0, bxt>>>(inp, 0, 0, FP0);
        run_gemm(gg0, Gh, Gl, Xth, Xtl, NN, NN, 32, 0, FP0, K50, 0, 0, 0);
        run_gemm(wgate, Ah, Al, Wg0h, Wg0l, K50, K50, 30, 1, FP0, K50, rub0, GATE, 0);
        // layer 0 candidate
        build_a<<<NB, FP0>>>(inp, 0, 1, FP0, K50);
        build_xt<<<xt0, bxt>>>(inp, 0, 1, FP0);
        run_gemm(gg0, Gh, Gl, Xth, Xtl, NN, NN, 32, 0, FP0, K50, 0, 0, 0);
        run_gemm(wcand, Ah, Al, Wc0h, Wc0l, K50, K50, 30, 2, FP0, K50, hb0, GATE, S0);
        // layer 1 gate
        build_a<<<NB, FP1>>>(inp, 1, 0, FP1, K51);
        build_xt<<<xt1, bxt>>>(inp, 1, 0, FP1);
        run_gemm(gg1, Gh, Gl, Xth, Xtl, NN, NN, 32, 0, FP1, K51, 0, 0, 0);
        run_gemm(wgate, Ah, Al, Wg1h, Wg1l, K51, K51, 40, 1, FP1, K51, rub1, GATE, 0);
        // layer 1 candidate
        build_a<<<NB, FP1>>>(inp, 1, 1, FP1, K51);
        build_xt<<<xt1, bxt>>>(inp, 1, 1, FP1);
        run_gemm(gg1, Gh, Gl, Xth, Xtl, NN, NN, 32, 0, FP1, K51, 0, 0, 0);
        run_gemm(wcand, Ah, Al, Wc1h, Wc1l, K51, K51, 40, 2, FP1, K51, hb1, GATE, S1);
    }
    write_out<<<NB, 128>>>(out);
}

// round 10
// speedup vs baseline: 3.0034x; 1.2436x over previous
#include <cuda_runtime.h>
#include <cuda_fp16.h>
#include <math.h>
#include <stdint.h>

#define NN 1024
#define BB 64
#define NB 65536
#define HH 128
#define F0R 130
#define FP0 160                  // layer0 padded features, [s(128), inp(2), 0...]
#define FP1 256
#define BF0 (BB*FP0)             // 10240
#define BF1 (BB*FP1)             // 16384
#define K50 (5*FP0)              // 800
#define K51 (5*FP1)              // 1280
#define PITCH 40                 // halves per smem row (80B, 16B-aligned, conflict-free)
#define TSH (128*PITCH)
#define SMEM_SZ (2*4*TSH*2)      // 81920

// ---------------- static device scratch ----------------
__device__ __align__(128) __half g_Ah[(size_t)NB*K51];
__device__ __align__(128) __half g_Al[(size_t)NB*K51];
__device__ __align__(128) __half g_Xth[(size_t)BF1*NN];
__device__ __align__(128) __half g_Xtl[(size_t)BF1*NN];
__device__ __align__(128) __half g_Gh[(size_t)4096*NN];
__device__ __align__(128) __half g_Gl[(size_t)4096*NN];
__device__ __align__(128) float  g_sq[(size_t)2*NN*NN];
__device__ __align__(128) __half g_Wg0h[256*K50], g_Wg0l[256*K50];
__device__ __align__(128) __half g_Wc0h[128*K50], g_Wc0l[128*K50];
__device__ __align__(128) __half g_Wg1h[256*K51], g_Wg1l[256*K51];
__device__ __align__(128) __half g_Wc1h[128*K51], g_Wc1l[128*K51];
__device__ __align__(128) float  g_gate[(size_t)NB*256];
__device__ __align__(128) float  g_s0[(size_t)NB*HH];
__device__ __align__(128) float  g_s1[(size_t)NB*HH];

// ---------------- helpers ----------------
__device__ __forceinline__ uint32_t smem_u32(const void* p){
    uint32_t a; asm("{ .reg .u64 t; cvta.to.shared.u64 t, %1; cvt.u32.u64 %0, t; }":"=r"(a):"l"(p)); return a;
}
__device__ __forceinline__ void cp16(uint32_t d, const void* s){
    asm volatile("cp.async.cg.shared.global [%0], [%1], 16;\n"::"r"(d),"l"(s):"memory");
}
__device__ __forceinline__ void ldmA(uint32_t* a, uint32_t addr){
    asm volatile("ldmatrix.sync.aligned.m8n8.x4.shared.b16 {%0,%1,%2,%3}, [%4];"
        : "=r"(a[0]),"=r"(a[1]),"=r"(a[2]),"=r"(a[3]) : "r"(addr));
}
__device__ __forceinline__ void ldmB(uint32_t* b, uint32_t addr){
    asm volatile("ldmatrix.sync.aligned.m8n8.x2.shared.b16 {%0,%1}, [%2];"
        : "=r"(b[0]),"=r"(b[1]) : "r"(addr));
}
__device__ __forceinline__ void mma16816(float* d, const uint32_t* a, const uint32_t* b){
    asm volatile("mma.sync.aligned.m16n8k16.row.col.f32.f16.f16.f32 "
        "{%0,%1,%2,%3},{%4,%5,%6,%7},{%8,%9},{%0,%1,%2,%3};"
        : "+f"(d[0]),"+f"(d[1]),"+f"(d[2]),"+f"(d[3])
        : "r"(a[0]),"r"(a[1]),"r"(a[2]),"r"(a[3]),"r"(b[0]),"r"(b[1]));
}

// ---------------- fp16-split HGEMM: quad-tile, 3 products per K-chunk ----------------
// acc = Ah@Bh^T + Ah@Bl^T + Al@Bh^T, K in chunks of 32; A,B K-major.
// mode 0: split-write Y into g_Ah/g_Al terms 1..4; B rows are (b*fCnt + j), feature f = fLo + j
// mode 1: gate[row*256+c] = sigmoid(v + bias[c])
// mode 2: state[row*128+c] = u*s + (1-u)*tanh(v + bias[c])
struct GArgs {
    const __half *Ah,*Al,*Bh,*Bl;
    int lda, ldb, nch, mode, fp, k5, fLo, fCnt;
    const float* bias; float* gate; float* state;
};

__global__ __launch_bounds__(256,2) void hgemm(GArgs g)
{
    extern __shared__ __align__(16) __half sm[];
    const int tid = threadIdx.x;
    const int wid = tid >> 5, lane = tid & 31;
    const int m0 = blockIdx.y * 128, n0 = blockIdx.x * 128;
    const int mbase = (wid >> 2) * 64, nbase = (wid & 3) * 32;
    const uint32_t smb = smem_u32(sm);

    float acc[4][4][4];
#pragma unroll
    for (int i = 0; i < 4; i++)
#pragma unroll
        for (int j = 0; j < 4; j++)
#pragma unroll
            for (int k = 0; k < 4; k++) acc[i][j][k] = 0.f;

    const int lr = tid >> 2;
    const int lc = (tid & 3) * 8;

    auto fill = [&](int c, int buf){
        const int k0 = c * 32;
        const __half* srcs[4] = {
            g.Ah + (size_t)m0 * g.lda + k0,
            g.Al + (size_t)m0 * g.lda + k0,
            g.Bh + (size_t)n0 * g.ldb + k0,
            g.Bl + (size_t)n0 * g.ldb + k0 };
        const int lds[4] = { g.lda, g.lda, g.ldb, g.ldb };
        const uint32_t base = smb + buf * 4*TSH*2;
#pragma unroll
        for (int t = 0; t < 4; t++) {
            const uint32_t tb = base + t * TSH*2;
#pragma unroll
            for (int h = 0; h < 2; h++) {
                const int r = lr + h * 64;
                cp16(tb + (r*PITCH + lc)*2, srcs[t] + (size_t)r * lds[t] + lc);
            }
        }
        asm volatile("cp.async.commit_group;\n":::"memory");
    };

    fill(0, 0);
    for (int c = 0; c < g.nch; c++) {
        const int buf = c & 1;
        if (c + 1 < g.nch) {
            fill(c + 1, buf ^ 1);
            asm volatile("cp.async.wait_group 1;\n":::"memory");
        } else {
            asm volatile("cp.async.wait_group 0;\n":::"memory");
        }
        __syncthreads();
        const uint32_t base = smb + buf * 4*TSH*2;
        const uint32_t aH = base, aL = base + TSH*2;
        const uint32_t bH = base + 2*TSH*2, bL = base + 3*TSH*2;
#pragma unroll
        for (int ks = 0; ks < 2; ks++) {
            const int chA = ks*16 + (lane >> 4) * 8;
            const int lB = lane & 15;
            const int chB = ks*16 + (lB >> 3) * 8;
            uint32_t afr[4][4], bfr[4][2];
            // product 1: Ah @ Bl
#pragma unroll
            for (int mi = 0; mi < 4; mi++) {
                const int r = mbase + mi*16 + (lane & 15);
                ldmA(afr[mi], aH + (r*PITCH + chA)*2);
            }
#pragma unroll
            for (int ni = 0; ni < 4; ni++) {
                const int r = nbase + ni*8 + (lB & 7);
                ldmB(bfr[ni], bL + (r*PITCH + chB)*2);
            }
#pragma unroll
            for (int mi = 0; mi < 4; mi++)
#pragma unroll
                for (int ni = 0; ni < 4; ni++)
                    mma16816(acc[mi][ni], afr[mi], bfr[ni]);
            // product 2: Ah @ Bh (reuse afr)
#pragma unroll
            for (int ni = 0; ni < 4; ni++) {
                const int r = nbase + ni*8 + (lB & 7);
                ldmB(bfr[ni], bH + (r*PITCH + chB)*2);
            }
#pragma unroll
            for (int mi = 0; mi < 4; mi++)
#pragma unroll
                for (int ni = 0; ni < 4; ni++)
                    mma16816(acc[mi][ni], afr[mi], bfr[ni]);
            // product 3: Al @ Bh (reuse bfr)
#pragma unroll
            for (int mi = 0; mi < 4; mi++) {
                const int r = mbase + mi*16 + (lane & 15);
                ldmA(afr[mi], aL + (r*PITCH + chA)*2);
            }
#pragma unroll
            for (int mi = 0; mi < 4; mi++)
#pragma unroll
                for (int ni = 0; ni < 4; ni++)
                    mma16816(acc[mi][ni], afr[mi], bfr[ni]);
        }
        __syncthreads();
    }

    // ---------------- epilogue ----------------
#pragma unroll
    for (int mi = 0; mi < 4; mi++) {
#pragma unroll
        for (int h2 = 0; h2 < 2; h2++) {
            const int rg = m0 + mbase + mi*16 + (lane >> 2) + h2*8;
#pragma unroll
            for (int ni = 0; ni < 4; ni++) {
                const int cg = n0 + nbase + ni*8 + (lane & 3)*2;
                const float v0 = acc[mi][ni][h2*2 + 0];
                const float v1 = acc[mi][ni][h2*2 + 1];
                if (g.mode == 0) {
                    const int s = rg >> 10, n = rg & 1023;
                    const int b = cg / g.fCnt;
                    const int f = g.fLo + (cg - b * g.fCnt);
                    const size_t base = (size_t)(n*64 + b) * g.k5 + (size_t)(s+1) * g.fp + f;
                    const __half h0 = __float2half_rn(v0), h1 = __float2half_rn(v1);
                    __half2 hh; hh.x = h0; hh.y = h1;
                    __half2 ll;
                    ll.x = __float2half_rn(v0 - __half2float(h0));
                    ll.y = __float2half_rn(v1 - __half2float(h1));
                    *(__half2*)(g_Ah + base) = hh;
                    *(__half2*)(g_Al + base) = ll;
                } else if (g.mode == 1) {
                    float2 o;
                    o.x = 1.f/(1.f + expf(-(v0 + g.bias[cg+0])));
                    o.y = 1.f/(1.f + expf(-(v1 + g.bias[cg+1])));
                    *(float2*)(g.gate + (size_t)rg*256 + cg) = o;
                } else {
                    const float2 u = *(const float2*)(g.gate + (size_t)rg*256 + 128 + cg);
                    const float2 so = *(const float2*)(g.state + (size_t)rg*128 + cg);
                    float2 o;
                    o.x = u.x*so.x + (1.f-u.x)*tanhf(v0 + g.bias[cg+0]);
                    o.y = u.y*so.y + (1.f-u.y)*tanhf(v1 + g.bias[cg+1]);
                    *(float2*)(g.state + (size_t)rg*128 + cg) = o;
                }
            }
        }
    }
}

// ---------------- fp32 SGEMM for prologue: C = 2 * A @ A (1024^3) ----------------
__global__ __launch_bounds__(256)
void sgemm_sq(const float* __restrict__ A, float* __restrict__ C)
{
    __shared__ float As[2][8][128];
    __shared__ float Bs[2][8][128];
    const int tid = threadIdx.x;
    const int m0 = blockIdx.y * 128, n0 = blockIdx.x * 128;
    const int arow = tid >> 1, acol = (tid & 1) << 2;
    const int brow = tid >> 5, bcol = (tid & 31) << 2;
    const float* Ap = A + (size_t)(m0 + arow) * NN + acol;
    const float* Bp = A + (size_t)brow * NN + n0 + bcol;
    const int tx = tid & 15, ty = tid >> 4;
    float acc[8][8];
#pragma unroll
    for (int i = 0; i < 8; i++)
#pragma unroll
        for (int j = 0; j < 8; j++) acc[i][j] = 0.f;
    float4 a4 = *(const float4*)Ap, b4 = *(const float4*)Bp;
    As[0][acol+0][arow]=a4.x; As[0][acol+1][arow]=a4.y; As[0][acol+2][arow]=a4.z; As[0][acol+3][arow]=a4.w;
    *(float4*)(&Bs[0][brow][bcol]) = b4;
    __syncthreads();
    for (int it = 0; it < 128; ++it) {
        const int buf = it & 1;
        if (it + 1 < 128) {
            const int k0 = (it + 1) << 3;
            a4 = *(const float4*)(Ap + k0);
            b4 = *(const float4*)(Bp + (size_t)k0 * NN);
        }
#pragma unroll
        for (int kk = 0; kk < 8; ++kk) {
            float ar[8], br[8];
            *(float4*)&ar[0] = *(const float4*)&As[buf][kk][ty*8];
            *(float4*)&ar[4] = *(const float4*)&As[buf][kk][ty*8+4];
            *(float4*)&br[0] = *(const float4*)&Bs[buf][kk][tx*8];
            *(float4*)&br[4] = *(const float4*)&Bs[buf][kk][tx*8+4];
#pragma unroll
            for (int i = 0; i < 8; i++)
#pragma unroll
                for (int j = 0; j < 8; j++) acc[i][j] = fmaf(ar[i], br[j], acc[i][j]);
        }
        if (it + 1 < 128) {
            const int nb2 = buf ^ 1;
            As[nb2][acol+0][arow]=a4.x; As[nb2][acol+1][arow]=a4.y; As[nb2][acol+2][arow]=a4.z; As[nb2][acol+3][arow]=a4.w;
            *(float4*)(&Bs[nb2][brow][bcol]) = b4;
            __syncthreads();
        }
    }
#pragma unroll
    for (int i = 0; i < 8; i++) {
        float* Cp = C + (size_t)(m0 + ty*8 + i) * NN + n0 + tx*8;
#pragma unroll
        for (int j = 0; j < 8; j++) Cp[j] = 2.f * acc[i][j];
    }
}

// ---------------- builders ----------------
// layer0 feature order: [s(128), inp(2), pad(30)]
__device__ __forceinline__ float xval0(const float* __restrict__ inp, int n, int b, int f, int reset){
    if (f < 128) {
        float s = g_s0[((size_t)n*64 + b)*HH + f];
        if (reset) s *= g_gate[((size_t)n*64 + b)*256 + f];
        return s;
    }
    if (f < 130) return inp[((size_t)b*NN + n)*2 + (f - 128)];
    return 0.f;
}
// layer1 feature order: [s0(128), s1(128)]
__device__ __forceinline__ float xval1(int n, int b, int f, int reset){
    if (f < HH) return g_s0[((size_t)n*64 + b)*HH + f];
    const int j = f - HH;
    float s = g_s1[((size_t)n*64 + b)*HH + j];
    if (reset) s *= g_gate[((size_t)n*64 + b)*256 + j];
    return s;
}

__global__ void build_a(const float* __restrict__ inp, int layer, int reset, int fp, int k5){
    const int row = blockIdx.x, f = threadIdx.x;
    const int n = row >> 6, b = row & 63;
    const float v = layer ? xval1(n, b, f, reset) : xval0(inp, n, b, f, reset);
    __half h = __float2half_rn(v);
    g_Ah[(size_t)row*k5 + f] = h;
    g_Al[(size_t)row*k5 + f] = __float2half_rn(v - __half2float(h));
}

// writes Xt rows (b*fCnt + j)*NN + n for features f = fLo + j, j in [0, fCnt)
__global__ void build_xt(const float* __restrict__ inp, int layer, int reset, int fLo, int fCnt){
    __shared__ float t[32][33];
    const int b = blockIdx.z, j0 = blockIdx.y*32, nt = blockIdx.x*32;
    const int tx = threadIdx.x, ty = threadIdx.y;
#pragma unroll
    for (int k = 0; k < 4; k++) {
        const int n = nt + ty + 8*k, f = fLo + j0 + tx;
        t[ty + 8*k][tx] = layer ? xval1(n, b, f, reset) : xval0(inp, n, b, f, reset);
    }
    __syncthreads();
#pragma unroll
    for (int k = 0; k < 4; k++) {
        const int j = j0 + ty + 8*k, n = nt + tx;
        const float v = t[tx][ty + 8*k];
        __half h = __float2half_rn(v);
        const size_t o = ((size_t)b*fCnt + j)*NN + n;
        g_Xth[o] = h;
        g_Xtl[o] = __float2half_rn(v - __half2float(h));
    }
}

__global__ void split_G(const float* __restrict__ sup){
    size_t i = (size_t)blockIdx.x * blockDim.x + threadIdx.x;
    if (i >= (size_t)4096*NN) return;
    const int row = (int)(i >> 10), col = (int)(i & 1023);
    const int slice = row >> 10, n = row & 1023;
    float v;
    if (slice == 0)      v = sup[(size_t)n*NN + col];
    else if (slice == 1) v = g_sq[(size_t)n*NN + col];
    else if (slice == 2) v = sup[(size_t)NN*NN + (size_t)n*NN + col];
    else                 v = g_sq[(size_t)NN*NN + (size_t)n*NN + col];
    __half h = __float2half_rn(v);
    g_Gh[i] = h;
    g_Gl[i] = __float2half_rn(v - __half2float(h));
}

// swapInp: layer0 reorder — W row for new f: f<128 -> orig 2+f; f in [128,130) -> orig f-128; else 0
__global__ void build_wt(__half* __restrict__ Wh, __half* __restrict__ Wl,
                         const float* __restrict__ src, int O, int F, int fp, int swapInp){
    const int k5 = 5*fp;
    int i = blockIdx.x * blockDim.x + threadIdx.x;
    if (i >= O*k5) return;
    const int o = i / k5, k = i - o*k5;
    const int t = k / fp, f = k - t*fp;
    int fo = f;
    if (swapInp) fo = (f < 128) ? (f + 2) : ((f < 130) ? (f - 128) : F);
    float v = 0.f;
    if (fo < F) {
        #define WSK(s,kx) src[((((size_t)(s))*3 + (kx))*F + fo)*O + o]
        switch (t) {
            case 0: v = WSK(0,0)+WSK(1,0)-WSK(0,2)-WSK(1,2); break;
            case 1: v = WSK(0,1); break;
            case 2: v = WSK(0,2); break;
            case 3: v = WSK(1,1); break;
            case 4: v = WSK(1,2); break;
        }
        #undef WSK
    }
    __half h = __float2half_rn(v);
    Wh[i] = h;
    Wl[i] = __float2half_rn(v - __half2float(h));
}

__global__ void write_out(float* __restrict__ out){
    const int nb = blockIdx.x, h = threadIdx.x;
    const int n = nb >> 6, b = nb & 63;
    out[(((size_t)0*BB + b)*NN + n)*HH + h] = g_s0[(size_t)nb*HH + h];
    out[(((size_t)1*BB + b)*NN + n)*HH + h] = g_s1[(size_t)nb*HH + h];
}

// ---------------- host ----------------
static void run_gemm(dim3 grid, const __half* Ah, const __half* Al,
                     const __half* Bh, const __half* Bl,
                     int lda, int ldb, int nch, int mode, int fp, int k5,
                     int fLo, int fCnt,
                     const float* bias, float* gate, float* state)
{
    GArgs g{Ah,Al,Bh,Bl,lda,ldb,nch,mode,fp,k5,fLo,fCnt,bias,gate,state};
    hgemm<<<grid, 256, SMEM_SZ>>>(g);
}

extern "C" void kernel_launch(void* const* d_in, const int* in_sizes, int n_in,
                              void* d_out, int out_size)
{
    const float* inputs = (const float*)d_in[0];
    const float* sup    = (const float*)d_in[1];
    const float* ruW0 = (const float*)d_in[2];
    const float* rub0 = (const float*)d_in[3];
    const float* hW0  = (const float*)d_in[4];
    const float* hb0  = (const float*)d_in[5];
    const float* ruW1 = (const float*)d_in[6];
    const float* rub1 = (const float*)d_in[7];
    const float* hW1  = (const float*)d_in[8];
    const float* hb1  = (const float*)d_in[9];
    float* out = (float*)d_out;

    cudaFuncSetAttribute(hgemm, cudaFuncAttributeMaxDynamicSharedMemorySize, SMEM_SZ);

    float *SQ, *S0, *S1, *GATE;
    __half *Ah, *Al, *Xth, *Xtl, *Gh, *Gl;
    __half *Wg0h,*Wg0l,*Wc0h,*Wc0l,*Wg1h,*Wg1l,*Wc1h,*Wc1l;
    cudaGetSymbolAddress((void**)&SQ, g_sq);
    cudaGetSymbolAddress((void**)&S0, g_s0);
    cudaGetSymbolAddress((void**)&S1, g_s1);
    cudaGetSymbolAddress((void**)&GATE, g_gate);
    cudaGetSymbolAddress((void**)&Ah, g_Ah);
    cudaGetSymbolAddress((void**)&Al, g_Al);
    cudaGetSymbolAddress((void**)&Xth, g_Xth);
    cudaGetSymbolAddress((void**)&Xtl, g_Xtl);
    cudaGetSymbolAddress((void**)&Gh, g_Gh);
    cudaGetSymbolAddress((void**)&Gl, g_Gl);
    cudaGetSymbolAddress((void**)&Wg0h, g_Wg0h); cudaGetSymbolAddress((void**)&Wg0l, g_Wg0l);
    cudaGetSymbolAddress((void**)&Wc0h, g_Wc0h); cudaGetSymbolAddress((void**)&Wc0l, g_Wc0l);
    cudaGetSymbolAddress((void**)&Wg1h, g_Wg1h); cudaGetSymbolAddress((void**)&Wg1l, g_Wg1l);
    cudaGetSymbolAddress((void**)&Wc1h, g_Wc1h); cudaGetSymbolAddress((void**)&Wc1l, g_Wc1l);

    // prologue
    sgemm_sq<<<dim3(8,8), 256>>>(sup, SQ);
    sgemm_sq<<<dim3(8,8), 256>>>(sup + (size_t)NN*NN, SQ + (size_t)NN*NN);
    split_G<<<(4096*1024)/256, 256>>>(sup);
    build_wt<<<(256*K50+255)/256, 256>>>(Wg0h, Wg0l, ruW0, 256, F0R, FP0, 1);
    build_wt<<<(128*K50+255)/256, 256>>>(Wc0h, Wc0l, hW0, 128, F0R, FP0, 1);
    build_wt<<<(256*K51+255)/256, 256>>>(Wg1h, Wg1l, ruW1, 256, FP1, FP1, 0);
    build_wt<<<(128*K51+255)/256, 256>>>(Wc1h, Wc1l, hW1, 128, FP1, FP1, 0);
    cudaMemsetAsync(S0, 0, (size_t)NB*HH*4);
    cudaMemsetAsync(S1, 0, (size_t)NB*HH*4);

    const dim3 gg0(BF0/128, 32);        // (80, 32)  layer0 gate graph
    const dim3 gg1(BF1/128, 32);        // (128, 32) layer1 gate graph
    const dim3 gcand(64, 32);           // candidate graph (128 feats x 64 batch)
    const dim3 wgate(2, 512), wcand(1, 512);
    const dim3 xtf0(32, FP0/32, BB), xtf1(32, FP1/32, BB), xtc(32, 4, BB);
    const dim3 bxt(32, 8);

    for (int t = 0; t < 12; ++t) {
        const float* inp = inputs + (size_t)t * BB * NN * 2;
        // ---- layer 0 gate: full X ----
        build_a<<<NB, FP0>>>(inp, 0, 0, FP0, K50);
        build_xt<<<xtf0, bxt>>>(inp, 0, 0, 0, FP0);
        run_gemm(gg0, Gh, Gl, Xth, Xtl, NN, NN, 32, 0, FP0, K50, 0, FP0, 0, 0, 0);
        run_gemm(wgate, Ah, Al, Wg0h, Wg0l, K50, K50, 25, 1, FP0, K50, 0, 0, rub0, GATE, 0);
        // ---- layer 0 candidate: only s-features (f 0..127) change ----
        build_a<<<NB, FP0>>>(inp, 0, 1, FP0, K50);
        build_xt<<<xtc, bxt>>>(inp, 0, 1, 0, 128);
        run_gemm(gcand, Gh, Gl, Xth, Xtl, NN, NN, 32, 0, FP0, K50, 0, 128, 0, 0, 0);
        run_gemm(wcand, Ah, Al, Wc0h, Wc0l, K50, K50, 25, 2, FP0, K50, 0, 0, hb0, GATE, S0);
        // ---- layer 1 gate: full X ----
        build_a<<<NB, FP1>>>(inp, 1, 0, FP1, K51);
        build_xt<<<xtf1, bxt>>>(inp, 1, 0, 0, FP1);
        run_gemm(gg1, Gh, Gl, Xth, Xtl, NN, NN, 32, 0, FP1, K51, 0, FP1, 0, 0, 0);
        run_gemm(wgate, Ah, Al, Wg1h, Wg1l, K51, K51, 40, 1, FP1, K51, 0, 0, rub1, GATE, 0);
        // ---- layer 1 candidate: only s1-features (f 128..255) change ----
        build_a<<<NB, FP1>>>(inp, 1, 1, FP1, K51);
        build_xt<<<xtc, bxt>>>(inp, 1, 1, 128, 128);
        run_gemm(gcand, Gh, Gl, Xth, Xtl, NN, NN, 32, 0, FP1, K51, 128, 128, 0, 0, 0);
        run_gemm(wcand, Ah, Al, Wc1h, Wc1l, K51, K51, 40, 2, FP1, K51, 0, 0, hb1, GATE, S1);
    }
    write_out<<<NB, 128>>>(out);
}